// round 11
// baseline (speedup 1.0000x reference)
#include <cuda_runtime.h>
#include <cuda_bf16.h>
#include <cstdint>

#define EDGES      2048
#define DIM        200
#define CH         50
#define KDIM       10000
#define NBLK       4
#define MROWS      8192
#define NNODES     40943
#define GSPLIT     2
#define KG_ROW     1250           // KDIM / 8
#define B_GROUPS   977            // ceil(DIM * KG_ROW / 256)
#define CPART_STRIDE (MROWS * DIM)

// ------------------------- static scratch (no allocs) -----------------------
__device__ __align__(16) __nv_bfloat16 g_Ahi[(size_t)MROWS * KDIM];   // 163.8 MB
__device__ __align__(16) __nv_bfloat16 g_Bhi[(size_t)DIM * KDIM];     // 4 MB
__device__ __align__(16) __nv_bfloat16 g_Blo[(size_t)DIM * KDIM];     // 4 MB
__device__ float g_scc[NBLK * CH];            // compact BN1 scale per (blk,ch)
__device__ float g_shc[NBLK * CH];            // compact BN1 shift per (blk,ch)
__device__ __align__(16) float g_Cpart[(size_t)GSPLIT * MROWS * DIM]; // 13.1 MB
__device__ __align__(16) float g_Y[MROWS * DIM];
__device__ __align__(16) float g_bn2s[NBLK * DIM];
__device__ __align__(16) float g_bn2h[NBLK * DIM];
__device__ float g_eps[NBLK * CH * EDGES];    // per-edge BN1 partial sums
__device__ float g_eq[NBLK * CH * EDGES];     // per-edge BN1 partial sumsq

// ------------------------------- helpers ------------------------------------
__device__ __forceinline__ float bn_relu(float a, float s, float h) {
    return fmaxf(fmaf(a, s, h), 0.0f);
}

__device__ __forceinline__ uint32_t smem_u32(const void* p) {
    uint32_t a;
    asm("{ .reg .u64 t; cvta.to.shared.u64 t, %1; cvt.u32.u64 %0, t; }" : "=r"(a) : "l"(p));
    return a;
}

__device__ __forceinline__ void ldsm4(uint32_t* r, uint32_t a) {
    asm volatile("ldmatrix.sync.aligned.m8n8.x4.shared.b16 {%0,%1,%2,%3}, [%4];"
                 : "=r"(r[0]), "=r"(r[1]), "=r"(r[2]), "=r"(r[3]) : "r"(a));
}

__device__ __forceinline__ void mma16816(float* c, const uint32_t* a,
                                         uint32_t b0, uint32_t b1) {
    asm volatile(
        "mma.sync.aligned.m16n8k16.row.col.f32.bf16.bf16.f32 "
        "{%0,%1,%2,%3}, {%4,%5,%6,%7}, {%8,%9}, {%0,%1,%2,%3};"
        : "+f"(c[0]), "+f"(c[1]), "+f"(c[2]), "+f"(c[3])
        : "r"(a[0]), "r"(a[1]), "r"(a[2]), "r"(a[3]), "r"(b0), "r"(b1));
}

__device__ __forceinline__ uint32_t pack_bf2(float a, float b) {
    __nv_bfloat162 t = __floats2bfloat162_rn(a, b);
    return *reinterpret_cast<uint32_t*>(&t);
}

__device__ __forceinline__ uint4 round8(const float* v) {
    uint4 HI;
    HI.x = pack_bf2(v[0], v[1]); HI.y = pack_bf2(v[2], v[3]);
    HI.z = pack_bf2(v[4], v[5]); HI.w = pack_bf2(v[6], v[7]);
    return HI;
}

__device__ __forceinline__ void split8(const float* v, uint4& HI, uint4& LO) {
    float hf[8], lf[8];
#pragma unroll
    for (int u = 0; u < 8; u++) {
        __nv_bfloat16 h = __float2bfloat16(v[u]);
        hf[u] = __bfloat162float(h);
        lf[u] = v[u] - hf[u];
    }
    HI.x = pack_bf2(hf[0], hf[1]); HI.y = pack_bf2(hf[2], hf[3]);
    HI.z = pack_bf2(hf[4], hf[5]); HI.w = pack_bf2(hf[6], hf[7]);
    LO.x = pack_bf2(lf[0], lf[1]); LO.y = pack_bf2(lf[2], lf[3]);
    LO.z = pack_bf2(lf[4], lf[5]); LO.w = pack_bf2(lf[6], lf[7]);
}

// ----------------- shared conv tile computation (into smem) -----------------
__device__ __forceinline__ void conv_tile(
    int e, int b, int tid,
    const float* __restrict__ pre_emb, const float* __restrict__ r_emb,
    const float* __restrict__ W2, const float* __restrict__ b2,
    const float* __restrict__ W3, const float* __restrict__ b3,
    const float* __restrict__ W4, const float* __restrict__ b4,
    const int* __restrict__ src_ids, const int* __restrict__ edge_type,
    const int* __restrict__ p1, const int* __restrict__ p2,
    const int* __restrict__ p3,
    float* ys, float (*xs)[204], float* ws, float* bsm)
{
    int Cin; const float* W; const float* bias;
    int rel0 = 0, rel1 = 0, rel2 = 0;
    if (b == 0)      { Cin = 2; W = W2; bias = b2; rel0 = p1[e]; }
    else if (b == 1) { Cin = 3; W = W3; bias = b3; rel0 = p2[2*e]; rel1 = p2[2*e+1]; }
    else if (b == 2) { Cin = 4; W = W4; bias = b4; rel0 = p3[3*e]; rel1 = p3[3*e+1]; rel2 = p3[3*e+2]; }
    else             { Cin = 2; W = W2; bias = b2; rel0 = edge_type[e]; }

    const int sid = src_ids[e];
    const float* srcs[4];
    srcs[0] = pre_emb + (size_t)sid  * DIM;
    srcs[1] = r_emb   + (size_t)rel0 * DIM;
    srcs[2] = r_emb   + (size_t)rel1 * DIM;
    srcs[3] = r_emb   + (size_t)rel2 * DIM;

    for (int i = tid; i < Cin * DIM; i += 256) {
        int ch = i / DIM, d = i - ch * DIM;
        xs[ch][d + 1] = srcs[ch][d];
    }
    if (tid < 8) xs[tid >> 1][(tid & 1) ? 201 : 0] = 0.0f;
    for (int i = tid; i < CH * Cin * 3; i += 256) ws[i] = W[i];
    if (tid < CH) bsm[tid] = bias[tid];
    __syncthreads();

    for (int idx = tid; idx < KDIM; idx += 256) {
        int c = idx / DIM, d = idx - c * DIM;
        float y = bsm[c];
        const float* wc = ws + c * Cin * 3;
        for (int i2 = 0; i2 < Cin; i2++)
            y += wc[i2*3+0] * xs[i2][d] + wc[i2*3+1] * xs[i2][d+1] + wc[i2*3+2] * xs[i2][d+2];
        ys[idx] = y;
    }
    __syncthreads();
}

// ------ K1: conv (smem only) + per-edge BN1 partial sums (deterministic) ----
__global__ void conv_stats_kernel(
    const float* __restrict__ pre_emb, const float* __restrict__ r_emb,
    const float* __restrict__ W2, const float* __restrict__ b2,
    const float* __restrict__ W3, const float* __restrict__ b3,
    const float* __restrict__ W4, const float* __restrict__ b4,
    const int* __restrict__ src_ids, const int* __restrict__ edge_type,
    const int* __restrict__ p1, const int* __restrict__ p2,
    const int* __restrict__ p3)
{
    const int e = blockIdx.x;
    const int b = blockIdx.y;
    const int tid = threadIdx.x;

    __shared__ float ys[KDIM];
    __shared__ float xs[4][204];
    __shared__ float ws[CH * 4 * 3];
    __shared__ float bsm[CH];

    conv_tile(e, b, tid, pre_emb, r_emb, W2, b2, W3, b3, W4, b4,
              src_ids, edge_type, p1, p2, p3, ys, xs, ws, bsm);

    const int w    = tid >> 5;
    const int lane = tid & 31;
    for (int c = w; c < CH; c += 8) {
        float s = 0.f, q = 0.f;
        for (int d = lane; d < DIM; d += 32) {
            float v = ys[c * DIM + d];
            s += v; q += v * v;
        }
#pragma unroll
        for (int off = 16; off > 0; off >>= 1) {
            s += __shfl_xor_sync(0xffffffffu, s, off);
            q += __shfl_xor_sync(0xffffffffu, q, off);
        }
        if (lane == 0) {
            g_eps[(b * CH + c) * EDGES + e] = s;
            g_eq [(b * CH + c) * EDGES + e] = q;
        }
    }
}

// ------ K2: reduce per-edge partials -> compact per-channel scale/shift -----
__global__ void statsr_kernel(const float* __restrict__ g1v, const float* __restrict__ be1v) {
    const int bc  = blockIdx.x;        // 0..199
    const int c   = bc % CH;
    const int tid = threadIdx.x;

    __shared__ float ssum[256];
    __shared__ float ssq[256];

    float s = 0.f, q = 0.f;
#pragma unroll
    for (int u = 0; u < 8; u++) {
        const int e = tid + u * 256;
        s += g_eps[bc * EDGES + e];
        q += g_eq [bc * EDGES + e];
    }
    ssum[tid] = s; ssq[tid] = q;
    __syncthreads();
    for (int off = 128; off > 0; off >>= 1) {
        if (tid < off) { ssum[tid] += ssum[tid+off]; ssq[tid] += ssq[tid+off]; }
        __syncthreads();
    }
    if (tid == 0) {
        const float inv = 1.0f / (float)(EDGES * DIM);
        float mu  = ssum[0] * inv;
        float var = ssq[0] * inv - mu * mu;
        float sc  = g1v[c] * rsqrtf(var + 1e-5f);
        g_scc[bc] = sc;
        g_shc[bc] = be1v[c] - mu * sc;
    }
}

// ---- K3: recompute conv + BN1+ReLU+round -> g_Ahi ; split fc_w -> hi/lo ----
__global__ void convAB_kernel(
    const float* __restrict__ pre_emb, const float* __restrict__ r_emb,
    const float* __restrict__ W2, const float* __restrict__ b2,
    const float* __restrict__ W3, const float* __restrict__ b3,
    const float* __restrict__ W4, const float* __restrict__ b4,
    const int* __restrict__ src_ids, const int* __restrict__ edge_type,
    const int* __restrict__ p1, const int* __restrict__ p2,
    const int* __restrict__ p3, const float* __restrict__ Bw)
{
    const int gid = blockIdx.x;
    const int tid = threadIdx.x;

    if (gid < EDGES * NBLK) {
        const int e = gid & (EDGES - 1);
        const int b = gid >> 11;

        __shared__ float ys[KDIM];
        __shared__ float xs[4][204];
        __shared__ float ws[CH * 4 * 3];
        __shared__ float bsm[CH];
        __shared__ float ssc[CH];
        __shared__ float ssh[CH];

        if (tid < CH) {
            ssc[tid] = g_scc[b * CH + tid];
            ssh[tid] = g_shc[b * CH + tid];
        }
        conv_tile(e, b, tid, pre_emb, r_emb, W2, b2, W3, b3, W4, b4,
                  src_ids, edge_type, p1, p2, p3, ys, xs, ws, bsm);

        uint4* arow = (uint4*)(g_Ahi + (size_t)(b * EDGES + e) * KDIM);
        for (int g = tid; g < KG_ROW; g += 256) {
            const int k = g * 8;
            const int c = k / DIM;          // 8-group never crosses a channel
            const float sc = ssc[c], sh = ssh[c];
            float v[8];
#pragma unroll
            for (int u = 0; u < 8; u++) v[u] = bn_relu(ys[k + u], sc, sh);
            arow[g] = round8(v);
        }
    } else {
        const size_t i = (size_t)(gid - EDGES * NBLK) * 256 + tid;
        if (i < (size_t)DIM * KG_ROW) {
            const size_t off = i * 8;
            float4 x0 = *(const float4*)(Bw + off);
            float4 x1 = *(const float4*)(Bw + off + 4);
            float v[8] = {x0.x, x0.y, x0.z, x0.w, x1.x, x1.y, x1.z, x1.w};
            uint4 HI, LO;
            split8(v, HI, LO);
            ((uint4*)g_Bhi)[i] = HI;
            ((uint4*)g_Blo)[i] = LO;
        }
    }
}

// SMEM layout (bytes, per double-buffer half). bf16, row stride 48B, BN pad 224.
#define SMA    0
#define SMB_HI 6144
#define SMB_LO 16896
#define SMBUF  27648
#define SMTOT  55296

// ---- K4: mma.sync 2-product GEMM: Ahi*(Bhi+Blo), split-K=2 -----------------
// BM=128, BN=224 (200 valid), BK=16, 256 thr, warp grid 4(M)x2(N):
// each warp 32x112 -> 2 A-ldsm + 14 B-ldsm, 56 HMMA per k-step.
__global__ __launch_bounds__(256, 1) void gemm_mma_kernel() {
    extern __shared__ char smem[];
    const uint32_t sbase = smem_u32(smem);
    const int tid  = threadIdx.x;
    const int warp = tid >> 5;
    const int lane = tid & 31;
    const int wm   = warp >> 1;          // 0..3  (M)
    const int wn   = warp & 1;           // 0..1  (N)
    const int m0   = blockIdx.x * 128;
    const int ks   = blockIdx.y;

    const int kbeg  = ks ? 312 : 0;
    const int iters = ks ? 313 : 312;    // 625 total k16-steps

    // A loader: row = tid>>1, half = tid&1 (8 bf16 = 16B)
    const int a_row  = tid >> 1;
    const int a_half = tid & 1;
    const __nv_bfloat16* ahp = g_Ahi + (size_t)(m0 + a_row) * KDIM + a_half * 8;

    // B loader: 400 (n, half) segments, hi+lo each
    const int n0 = tid >> 1,         h0 = tid & 1;
    const int n1 = (tid + 256) >> 1;
    const bool has2 = (tid < 144);
    const __nv_bfloat16* b0hp = g_Bhi + (size_t)n0 * KDIM + h0 * 8;
    const __nv_bfloat16* b0lp = g_Blo + (size_t)n0 * KDIM + h0 * 8;
    const __nv_bfloat16* b1hp = g_Bhi + (size_t)n1 * KDIM + h0 * 8;
    const __nv_bfloat16* b1lp = g_Blo + (size_t)n1 * KDIM + h0 * 8;

    float acc[2][14][4];
#pragma unroll
    for (int i = 0; i < 2; i++)
#pragma unroll
        for (int j = 0; j < 14; j++)
#pragma unroll
            for (int q = 0; q < 4; q++) acc[i][j][q] = 0.f;

    uint4 rAH, rB0H, rB0L, rB1H, rB1L;

    // ---- prologue ----
    {
        const int k16 = kbeg * 16;
        rAH  = *(const uint4*)(ahp + k16);
        rB0H = *(const uint4*)(b0hp + k16);
        rB0L = *(const uint4*)(b0lp + k16);
        if (has2) {
            rB1H = *(const uint4*)(b1hp + k16);
            rB1L = *(const uint4*)(b1lp + k16);
        }
        char* base = smem;
        *(uint4*)(base + SMA + a_row * 48 + a_half * 16) = rAH;
        *(uint4*)(base + SMB_HI + n0 * 48 + h0 * 16) = rB0H;
        *(uint4*)(base + SMB_LO + n0 * 48 + h0 * 16) = rB0L;
        if (has2) {
            *(uint4*)(base + SMB_HI + n1 * 48 + h0 * 16) = rB1H;
            *(uint4*)(base + SMB_LO + n1 * 48 + h0 * 16) = rB1L;
        }
    }

    int p = 0;
    for (int t = 0; t < iters; t++) {
        __syncthreads();
        const bool more = (t + 1 < iters);
        if (more) {
            const int k16 = (kbeg + t + 1) * 16;
            rAH  = *(const uint4*)(ahp + k16);
            rB0H = *(const uint4*)(b0hp + k16);
            rB0L = *(const uint4*)(b0lp + k16);
            if (has2) {
                rB1H = *(const uint4*)(b1hp + k16);
                rB1L = *(const uint4*)(b1lp + k16);
            }
        }

        // ---- compute on buffer p ----
        {
            const uint32_t bufb = sbase + (p ? SMBUF : 0);
            uint32_t ah[2][4];
#pragma unroll
            for (int mt = 0; mt < 2; mt++) {
                const uint32_t aaddr = bufb + SMA
                    + (uint32_t)((wm * 32 + mt * 16 + (lane & 15)) * 48)
                    + (uint32_t)((lane >> 4) * 16);
                ldsm4(ah[mt], aaddr);
            }
#pragma unroll
            for (int pr = 0; pr < 7; pr++) {
                uint32_t bh[4], bl[4];
                const uint32_t ba = bufb + SMB_HI
                    + (uint32_t)((wn * 112 + pr * 16 + (lane & 15)) * 48)
                    + (uint32_t)((lane >> 4) * 16);
                ldsm4(bh, ba);
                ldsm4(bl, ba + (SMB_LO - SMB_HI));
#pragma unroll
                for (int mt = 0; mt < 2; mt++) {
                    mma16816(acc[mt][2*pr],   ah[mt], bh[0], bh[2]);
                    mma16816(acc[mt][2*pr],   ah[mt], bl[0], bl[2]);
                    mma16816(acc[mt][2*pr+1], ah[mt], bh[1], bh[3]);
                    mma16816(acc[mt][2*pr+1], ah[mt], bl[1], bl[3]);
                }
            }
        }

        // ---- store next tile into buffer q ----
        if (more) {
            char* base = smem + (p ? 0 : SMBUF);
            *(uint4*)(base + SMA + a_row * 48 + a_half * 16) = rAH;
            *(uint4*)(base + SMB_HI + n0 * 48 + h0 * 16) = rB0H;
            *(uint4*)(base + SMB_LO + n0 * 48 + h0 * 16) = rB0L;
            if (has2) {
                *(uint4*)(base + SMB_HI + n1 * 48 + h0 * 16) = rB1H;
                *(uint4*)(base + SMB_LO + n1 * 48 + h0 * 16) = rB1L;
            }
        }
        p ^= 1;
    }

    // ---- epilogue: acc -> split-K partial (guard n < 200) ----
    float* cp = g_Cpart + (size_t)ks * CPART_STRIDE;
#pragma unroll
    for (int mt = 0; mt < 2; mt++) {
        const int rb = m0 + wm * 32 + mt * 16 + (lane >> 2);
#pragma unroll
        for (int nt = 0; nt < 14; nt++) {
            const int n = wn * 112 + nt * 8 + (lane & 3) * 2;
            if (n < DIM) {
                *(float2*)(cp + (size_t)rb * DIM + n)       = make_float2(acc[mt][nt][0], acc[mt][nt][1]);
                *(float2*)(cp + (size_t)(rb + 8) * DIM + n) = make_float2(acc[mt][nt][2], acc[mt][nt][3]);
            }
        }
    }
}

// ------------------------------ K5: zero out --------------------------------
__global__ void zero_kernel(float4* __restrict__ out) {
    const size_t total  = (size_t)EDGES * NNODES / 4;
    const size_t stride = (size_t)gridDim.x * blockDim.x;
    for (size_t i = (size_t)blockIdx.x * blockDim.x + threadIdx.x; i < total; i += stride)
        out[i] = make_float4(0.f, 0.f, 0.f, 0.f);
}

// ----------------- K6: split-K reduce (fixed order) + fc_b ------------------
__global__ void reduce_kernel(const float* __restrict__ fc_b) {
    const int i = blockIdx.x * 256 + threadIdx.x;
    const float4* p = (const float4*)g_Cpart;
    const size_t stride4 = CPART_STRIDE / 4;
    float4 s = p[i];
    float4 v = p[stride4 + i];
    s.x += v.x; s.y += v.y; s.z += v.z; s.w += v.w;
    const int n0 = (i * 4) % DIM;
    float4 bb = *(const float4*)(fc_b + n0);
    s.x += bb.x; s.y += bb.y; s.z += bb.z; s.w += bb.w;
    ((float4*)g_Y)[i] = s;
}

// --------------------------- K7: BN2 stats ----------------------------------
__global__ void bn2_kernel(const float* __restrict__ g2v, const float* __restrict__ be2v) {
    const int b   = blockIdx.x / DIM;
    const int n   = blockIdx.x - b * DIM;
    const int tid = threadIdx.x;

    __shared__ float ssum[256];
    __shared__ float ssq[256];

    float s = 0.f, q = 0.f;
    const float* base = g_Y + (size_t)(b * EDGES) * DIM + n;
#pragma unroll
    for (int u = 0; u < 8; u++) {
        float v = base[(size_t)(tid + u * 256) * DIM];
        s += v; q += v * v;
    }
    ssum[tid] = s; ssq[tid] = q;
    __syncthreads();
    for (int off = 128; off > 0; off >>= 1) {
        if (tid < off) { ssum[tid] += ssum[tid+off]; ssq[tid] += ssq[tid+off]; }
        __syncthreads();
    }
    if (tid == 0) {
        const float inv = 1.0f / (float)EDGES;
        float mu  = ssum[0] * inv;
        float var = ssq[0] * inv - mu * mu;
        float sc  = g2v[n] * rsqrtf(var + 1e-5f);
        g_bn2s[b * DIM + n] = sc;
        g_bn2h[b * DIM + n] = be2v[n] - mu * sc;
    }
}

// ----------------- K8: BN2+ReLU, cosine, scatter to output ------------------
__global__ void final_kernel(const int* __restrict__ o, float* __restrict__ out) {
    const int e    = blockIdx.x * 8 + (threadIdx.x >> 5);
    const int lane = threadIdx.x & 31;

    float dot[3] = {0.f,0.f,0.f}, nx[3] = {0.f,0.f,0.f}, nre = 0.f;
    for (int f = lane; f < DIM; f += 32) {
        float re = bn_relu(g_Y[(size_t)(3 * EDGES + e) * DIM + f],
                           g_bn2s[3 * DIM + f], g_bn2h[3 * DIM + f]);
        nre += re * re;
#pragma unroll
        for (int b = 0; b < 3; b++) {
            float xb = bn_relu(g_Y[(size_t)(b * EDGES + e) * DIM + f],
                               g_bn2s[b * DIM + f], g_bn2h[b * DIM + f]);
            dot[b] += xb * re;
            nx[b]  += xb * xb;
        }
    }
#pragma unroll
    for (int off = 16; off > 0; off >>= 1) {
        nre += __shfl_xor_sync(0xffffffffu, nre, off);
#pragma unroll
        for (int b = 0; b < 3; b++) {
            dot[b] += __shfl_xor_sync(0xffffffffu, dot[b], off);
            nx[b]  += __shfl_xor_sync(0xffffffffu, nx[b], off);
        }
    }
    if (lane == 0) {
        float nr = sqrtf(nre);
        float c = 0.f;
#pragma unroll
        for (int b = 0; b < 3; b++)
            c += dot[b] / fmaxf(sqrtf(nx[b]) * nr, 1e-8f);
        out[(size_t)e * NNODES + o[e]] = c;
    }
}

// ---------------------------------------------------------------------------
extern "C" void kernel_launch(void* const* d_in, const int* in_sizes, int n_in,
                              void* d_out, int out_size) {
    const float* pre_emb  = (const float*)d_in[0];
    const float* r_emb    = (const float*)d_in[1];
    const float* W2       = (const float*)d_in[2];
    const float* b2       = (const float*)d_in[3];
    const float* W3       = (const float*)d_in[4];
    const float* b3       = (const float*)d_in[5];
    const float* W4       = (const float*)d_in[6];
    const float* b4       = (const float*)d_in[7];
    const float* fc_w     = (const float*)d_in[8];
    const float* fc_b     = (const float*)d_in[9];
    const float* g1       = (const float*)d_in[10];
    const float* be1      = (const float*)d_in[11];
    const float* g2       = (const float*)d_in[12];
    const float* be2      = (const float*)d_in[13];
    const int*   src_ids  = (const int*)d_in[14];
    const int*   edge_type= (const int*)d_in[15];
    const int*   p1       = (const int*)d_in[16];
    const int*   p2       = (const int*)d_in[17];
    const int*   p3       = (const int*)d_in[18];
    const int*   o        = (const int*)d_in[19];
    float* out = (float*)d_out;

    cudaFuncSetAttribute(gemm_mma_kernel,
                         cudaFuncAttributeMaxDynamicSharedMemorySize, SMTOT);

    conv_stats_kernel<<<dim3(EDGES, NBLK), 256>>>(pre_emb, r_emb, W2, b2, W3, b3, W4, b4,
                                                  src_ids, edge_type, p1, p2, p3);
    statsr_kernel<<<NBLK * CH, 256>>>(g1, be1);
    convAB_kernel<<<EDGES * NBLK + B_GROUPS, 256>>>(pre_emb, r_emb, W2, b2, W3, b3, W4, b4,
                                                    src_ids, edge_type, p1, p2, p3, fc_w);
    gemm_mma_kernel<<<dim3(MROWS / 128, GSPLIT), 256, SMTOT>>>();
    zero_kernel<<<4096, 256>>>((float4*)out);
    reduce_kernel<<<(MROWS * DIM / 4) / 256, 256>>>(fc_b);
    bn2_kernel<<<NBLK * DIM, 256>>>(g2, be2);
    final_kernel<<<EDGES / 8, 256>>>(o, out);
}

// round 13
// speedup vs baseline: 1.4224x; 1.4224x over previous
#include <cuda_runtime.h>
#include <cuda_bf16.h>
#include <cstdint>

#define EDGES      2048
#define DIM        200
#define CH         50
#define KDIM       10000
#define NBLK       4
#define MROWS      8192
#define NNODES     40943
#define GSPLIT     2
#define KG_ROW     1250           // KDIM / 8
#define A_GROUPS   40000          // MROWS * KG_ROW / 256
#define B_GROUPS   977            // ceil(DIM * KG_ROW / 256)
#define CPART_STRIDE (MROWS * DIM)

// ------------------------- static scratch (no allocs) -----------------------
__device__ __align__(16) float g_A[(size_t)NBLK * EDGES * KDIM];      // 327.7 MB
__device__ __align__(16) __nv_bfloat16 g_Ahi[(size_t)MROWS * KDIM];   // 163.8 MB
__device__ __align__(16) __nv_bfloat16 g_Bhi[(size_t)DIM * KDIM];     // 4 MB
__device__ __align__(16) __nv_bfloat16 g_Blo[(size_t)DIM * KDIM];     // 4 MB
__device__ float g_scc[NBLK * CH];            // compact BN1 scale per (blk,ch)
__device__ float g_shc[NBLK * CH];            // compact BN1 shift per (blk,ch)
__device__ __align__(16) float g_Cpart[(size_t)GSPLIT * MROWS * DIM]; // 13.1 MB
__device__ __align__(16) float g_Y[MROWS * DIM];
__device__ __align__(16) float g_bn2s[NBLK * DIM];
__device__ __align__(16) float g_bn2h[NBLK * DIM];
__device__ float g_eps[NBLK * CH * EDGES];    // per-edge BN1 partial sums
__device__ float g_eq[NBLK * CH * EDGES];     // per-edge BN1 partial sumsq

// ------------------------------- helpers ------------------------------------
__device__ __forceinline__ float bn_relu(float a, float s, float h) {
    return fmaxf(fmaf(a, s, h), 0.0f);
}

__device__ __forceinline__ uint32_t smem_u32(const void* p) {
    uint32_t a;
    asm("{ .reg .u64 t; cvta.to.shared.u64 t, %1; cvt.u32.u64 %0, t; }" : "=r"(a) : "l"(p));
    return a;
}

__device__ __forceinline__ void ldsm4(uint32_t* r, uint32_t a) {
    asm volatile("ldmatrix.sync.aligned.m8n8.x4.shared.b16 {%0,%1,%2,%3}, [%4];"
                 : "=r"(r[0]), "=r"(r[1]), "=r"(r[2]), "=r"(r[3]) : "r"(a));
}

__device__ __forceinline__ void mma16816(float* c, const uint32_t* a,
                                         uint32_t b0, uint32_t b1) {
    asm volatile(
        "mma.sync.aligned.m16n8k16.row.col.f32.bf16.bf16.f32 "
        "{%0,%1,%2,%3}, {%4,%5,%6,%7}, {%8,%9}, {%0,%1,%2,%3};"
        : "+f"(c[0]), "+f"(c[1]), "+f"(c[2]), "+f"(c[3])
        : "r"(a[0]), "r"(a[1]), "r"(a[2]), "r"(a[3]), "r"(b0), "r"(b1));
}

__device__ __forceinline__ uint32_t pack_bf2(float a, float b) {
    __nv_bfloat162 t = __floats2bfloat162_rn(a, b);
    return *reinterpret_cast<uint32_t*>(&t);
}

__device__ __forceinline__ uint4 round8(const float* v) {
    uint4 HI;
    HI.x = pack_bf2(v[0], v[1]); HI.y = pack_bf2(v[2], v[3]);
    HI.z = pack_bf2(v[4], v[5]); HI.w = pack_bf2(v[6], v[7]);
    return HI;
}

__device__ __forceinline__ void split8(const float* v, uint4& HI, uint4& LO) {
    float hf[8], lf[8];
#pragma unroll
    for (int u = 0; u < 8; u++) {
        __nv_bfloat16 h = __float2bfloat16(v[u]);
        hf[u] = __bfloat162float(h);
        lf[u] = v[u] - hf[u];
    }
    HI.x = pack_bf2(hf[0], hf[1]); HI.y = pack_bf2(hf[2], hf[3]);
    HI.z = pack_bf2(hf[4], hf[5]); HI.w = pack_bf2(hf[6], hf[7]);
    LO.x = pack_bf2(lf[0], lf[1]); LO.y = pack_bf2(lf[2], lf[3]);
    LO.z = pack_bf2(lf[4], lf[5]); LO.w = pack_bf2(lf[6], lf[7]);
}

// ------ K1: conv1d -> g_A + fused per-edge BN1 partials (warp/channel) ------
__global__ void conv_kernel(
    const float* __restrict__ pre_emb, const float* __restrict__ r_emb,
    const float* __restrict__ W2, const float* __restrict__ b2,
    const float* __restrict__ W3, const float* __restrict__ b3,
    const float* __restrict__ W4, const float* __restrict__ b4,
    const int* __restrict__ src_ids, const int* __restrict__ edge_type,
    const int* __restrict__ p1, const int* __restrict__ p2,
    const int* __restrict__ p3)
{
    const int e   = blockIdx.x;
    const int b   = blockIdx.y;
    const int tid = threadIdx.x;

    __shared__ float xs[4][204];      // halo: [0]=0, [1..200], [201]=0
    __shared__ float ws[CH * 4 * 3];
    __shared__ float bsm[CH];

    int Cin; const float* W; const float* bias;
    int rel0 = 0, rel1 = 0, rel2 = 0;
    if (b == 0)      { Cin = 2; W = W2; bias = b2; rel0 = p1[e]; }
    else if (b == 1) { Cin = 3; W = W3; bias = b3; rel0 = p2[2*e]; rel1 = p2[2*e+1]; }
    else if (b == 2) { Cin = 4; W = W4; bias = b4; rel0 = p3[3*e]; rel1 = p3[3*e+1]; rel2 = p3[3*e+2]; }
    else             { Cin = 2; W = W2; bias = b2; rel0 = edge_type[e]; }

    const int sid = src_ids[e];
    const float* srcs[4];
    srcs[0] = pre_emb + (size_t)sid  * DIM;
    srcs[1] = r_emb   + (size_t)rel0 * DIM;
    srcs[2] = r_emb   + (size_t)rel1 * DIM;
    srcs[3] = r_emb   + (size_t)rel2 * DIM;

    for (int i = tid; i < Cin * DIM; i += 256) {
        int ch = i / DIM, d = i - ch * DIM;
        xs[ch][d + 1] = srcs[ch][d];
    }
    if (tid < 8) xs[tid >> 1][(tid & 1) ? 201 : 0] = 0.0f;
    for (int i = tid; i < CH * Cin * 3; i += 256) ws[i] = W[i];
    if (tid < CH) bsm[tid] = bias[tid];
    __syncthreads();

    const int w    = tid >> 5;
    const int lane = tid & 31;
    float* outrow = g_A + (size_t)(b * EDGES + e) * KDIM;

    for (int c = w; c < CH; c += 8) {
        float wreg[12];
        const float* wc = ws + c * Cin * 3;
#pragma unroll
        for (int i2 = 0; i2 < 12; i2++) wreg[i2] = (i2 < Cin * 3) ? wc[i2] : 0.f;
        const float bv = bsm[c];

        float s = 0.f, q = 0.f;
        for (int d = lane; d < DIM; d += 32) {
            float y = bv;
            for (int i2 = 0; i2 < Cin; i2++)
                y += wreg[i2*3+0] * xs[i2][d] + wreg[i2*3+1] * xs[i2][d+1]
                   + wreg[i2*3+2] * xs[i2][d+2];
            outrow[c * DIM + d] = y;
            s += y; q += y * y;
        }
#pragma unroll
        for (int off = 16; off > 0; off >>= 1) {
            s += __shfl_xor_sync(0xffffffffu, s, off);
            q += __shfl_xor_sync(0xffffffffu, q, off);
        }
        if (lane == 0) {
            g_eps[(b * CH + c) * EDGES + e] = s;
            g_eq [(b * CH + c) * EDGES + e] = q;
        }
    }
}

// ------ K2: reduce per-edge partials -> compact per-channel scale/shift -----
__global__ void statsr_kernel(const float* __restrict__ g1v, const float* __restrict__ be1v) {
    const int bc  = blockIdx.x;        // 0..199
    const int c   = bc % CH;
    const int tid = threadIdx.x;

    __shared__ float ssum[256];
    __shared__ float ssq[256];

    float s = 0.f, q = 0.f;
#pragma unroll
    for (int u = 0; u < 8; u++) {
        const int e = tid + u * 256;
        s += g_eps[bc * EDGES + e];
        q += g_eq [bc * EDGES + e];
    }
    ssum[tid] = s; ssq[tid] = q;
    __syncthreads();
    for (int off = 128; off > 0; off >>= 1) {
        if (tid < off) { ssum[tid] += ssum[tid+off]; ssq[tid] += ssq[tid+off]; }
        __syncthreads();
    }
    if (tid == 0) {
        const float inv = 1.0f / (float)(EDGES * DIM);
        float mu  = ssum[0] * inv;
        float var = ssq[0] * inv - mu * mu;
        float sc  = g1v[c] * rsqrtf(var + 1e-5f);
        g_scc[bc] = sc;
        g_shc[bc] = be1v[c] - mu * sc;
    }
}

// ---- K3: BN1+ReLU+round A -> g_Ahi (bf16); split fc_w -> hi/lo bf16 --------
__global__ void splitAB_kernel(const float* __restrict__ Bw) {
    const int gid = blockIdx.x;
    const int tid = threadIdx.x;

    if (gid < A_GROUPS) {
        const size_t i = (size_t)gid * 256 + tid;   // 8-elt group id
        const int m  = (int)(i / KG_ROW);
        const int kg = (int)(i - (size_t)m * KG_ROW);
        const int k  = kg * 8;
        const int c  = k / DIM;                     // group never crosses channel
        const int blk = m >> 11;
        const float sc = __ldg(g_scc + blk * CH + c);
        const float sh = __ldg(g_shc + blk * CH + c);

        const size_t off = (size_t)m * KDIM + k;
        float4 x0 = *(const float4*)(g_A + off);
        float4 x1 = *(const float4*)(g_A + off + 4);

        float v[8];
        v[0] = bn_relu(x0.x, sc, sh); v[1] = bn_relu(x0.y, sc, sh);
        v[2] = bn_relu(x0.z, sc, sh); v[3] = bn_relu(x0.w, sc, sh);
        v[4] = bn_relu(x1.x, sc, sh); v[5] = bn_relu(x1.y, sc, sh);
        v[6] = bn_relu(x1.z, sc, sh); v[7] = bn_relu(x1.w, sc, sh);

        ((uint4*)g_Ahi)[i] = round8(v);
    } else {
        const size_t i = (size_t)(gid - A_GROUPS) * 256 + tid;
        if (i < (size_t)DIM * KG_ROW) {
            const size_t off = i * 8;
            float4 x0 = *(const float4*)(Bw + off);
            float4 x1 = *(const float4*)(Bw + off + 4);
            float v[8] = {x0.x, x0.y, x0.z, x0.w, x1.x, x1.y, x1.z, x1.w};
            uint4 HI, LO;
            split8(v, HI, LO);
            ((uint4*)g_Bhi)[i] = HI;
            ((uint4*)g_Blo)[i] = LO;
        }
    }
}

// SMEM layout (bytes, per double-buffer half). bf16, row stride 48B, BN pad 224.
#define SMA    0
#define SMB_HI 6144
#define SMB_LO 16896
#define SMBUF  27648
#define SMTOT  55296

// ---- K4: mma.sync 2-product GEMM: Ahi*(Bhi+Blo), split-K=2 -----------------
// BM=128, BN=224 (200 valid), BK=16, 256 thr, warp grid 4(M)x2(N):
// each warp 32x112 -> 2 A-ldsm + 14 B-ldsm, 56 HMMA per k-step.
__global__ __launch_bounds__(256, 1) void gemm_mma_kernel() {
    extern __shared__ char smem[];
    const uint32_t sbase = smem_u32(smem);
    const int tid  = threadIdx.x;
    const int warp = tid >> 5;
    const int lane = tid & 31;
    const int wm   = warp >> 1;          // 0..3  (M)
    const int wn   = warp & 1;           // 0..1  (N)
    const int m0   = blockIdx.x * 128;
    const int ks   = blockIdx.y;

    const int kbeg  = ks ? 312 : 0;
    const int iters = ks ? 313 : 312;    // 625 total k16-steps

    // A loader: row = tid>>1, half = tid&1 (8 bf16 = 16B)
    const int a_row  = tid >> 1;
    const int a_half = tid & 1;
    const __nv_bfloat16* ahp = g_Ahi + (size_t)(m0 + a_row) * KDIM + a_half * 8;

    // B loader: 400 (n, half) segments, hi+lo each
    const int n0 = tid >> 1,         h0 = tid & 1;
    const int n1 = (tid + 256) >> 1;
    const bool has2 = (tid < 144);
    const __nv_bfloat16* b0hp = g_Bhi + (size_t)n0 * KDIM + h0 * 8;
    const __nv_bfloat16* b0lp = g_Blo + (size_t)n0 * KDIM + h0 * 8;
    const __nv_bfloat16* b1hp = g_Bhi + (size_t)n1 * KDIM + h0 * 8;
    const __nv_bfloat16* b1lp = g_Blo + (size_t)n1 * KDIM + h0 * 8;

    float acc[2][14][4];
#pragma unroll
    for (int i = 0; i < 2; i++)
#pragma unroll
        for (int j = 0; j < 14; j++)
#pragma unroll
            for (int q = 0; q < 4; q++) acc[i][j][q] = 0.f;

    uint4 rAH, rB0H, rB0L, rB1H, rB1L;

    // ---- prologue ----
    {
        const int k16 = kbeg * 16;
        rAH  = *(const uint4*)(ahp + k16);
        rB0H = *(const uint4*)(b0hp + k16);
        rB0L = *(const uint4*)(b0lp + k16);
        if (has2) {
            rB1H = *(const uint4*)(b1hp + k16);
            rB1L = *(const uint4*)(b1lp + k16);
        }
        char* base = smem;
        *(uint4*)(base + SMA + a_row * 48 + a_half * 16) = rAH;
        *(uint4*)(base + SMB_HI + n0 * 48 + h0 * 16) = rB0H;
        *(uint4*)(base + SMB_LO + n0 * 48 + h0 * 16) = rB0L;
        if (has2) {
            *(uint4*)(base + SMB_HI + n1 * 48 + h0 * 16) = rB1H;
            *(uint4*)(base + SMB_LO + n1 * 48 + h0 * 16) = rB1L;
        }
    }

    int p = 0;
    for (int t = 0; t < iters; t++) {
        __syncthreads();
        const bool more = (t + 1 < iters);
        if (more) {
            const int k16 = (kbeg + t + 1) * 16;
            rAH  = *(const uint4*)(ahp + k16);
            rB0H = *(const uint4*)(b0hp + k16);
            rB0L = *(const uint4*)(b0lp + k16);
            if (has2) {
                rB1H = *(const uint4*)(b1hp + k16);
                rB1L = *(const uint4*)(b1lp + k16);
            }
        }

        // ---- compute on buffer p ----
        {
            const uint32_t bufb = sbase + (p ? SMBUF : 0);
            uint32_t ah[2][4];
#pragma unroll
            for (int mt = 0; mt < 2; mt++) {
                const uint32_t aaddr = bufb + SMA
                    + (uint32_t)((wm * 32 + mt * 16 + (lane & 15)) * 48)
                    + (uint32_t)((lane >> 4) * 16);
                ldsm4(ah[mt], aaddr);
            }
#pragma unroll
            for (int pr = 0; pr < 7; pr++) {
                uint32_t bh[4], bl[4];
                const uint32_t ba = bufb + SMB_HI
                    + (uint32_t)((wn * 112 + pr * 16 + (lane & 15)) * 48)
                    + (uint32_t)((lane >> 4) * 16);
                ldsm4(bh, ba);
                ldsm4(bl, ba + (SMB_LO - SMB_HI));
#pragma unroll
                for (int mt = 0; mt < 2; mt++) {
                    mma16816(acc[mt][2*pr],   ah[mt], bh[0], bh[2]);
                    mma16816(acc[mt][2*pr],   ah[mt], bl[0], bl[2]);
                    mma16816(acc[mt][2*pr+1], ah[mt], bh[1], bh[3]);
                    mma16816(acc[mt][2*pr+1], ah[mt], bl[1], bl[3]);
                }
            }
        }

        // ---- store next tile into buffer q ----
        if (more) {
            char* base = smem + (p ? 0 : SMBUF);
            *(uint4*)(base + SMA + a_row * 48 + a_half * 16) = rAH;
            *(uint4*)(base + SMB_HI + n0 * 48 + h0 * 16) = rB0H;
            *(uint4*)(base + SMB_LO + n0 * 48 + h0 * 16) = rB0L;
            if (has2) {
                *(uint4*)(base + SMB_HI + n1 * 48 + h0 * 16) = rB1H;
                *(uint4*)(base + SMB_LO + n1 * 48 + h0 * 16) = rB1L;
            }
        }
        p ^= 1;
    }

    // ---- epilogue: acc -> split-K partial (guard n < 200) ----
    float* cp = g_Cpart + (size_t)ks * CPART_STRIDE;
#pragma unroll
    for (int mt = 0; mt < 2; mt++) {
        const int rb = m0 + wm * 32 + mt * 16 + (lane >> 2);
#pragma unroll
        for (int nt = 0; nt < 14; nt++) {
            const int n = wn * 112 + nt * 8 + (lane & 3) * 2;
            if (n < DIM) {
                *(float2*)(cp + (size_t)rb * DIM + n)       = make_float2(acc[mt][nt][0], acc[mt][nt][1]);
                *(float2*)(cp + (size_t)(rb + 8) * DIM + n) = make_float2(acc[mt][nt][2], acc[mt][nt][3]);
            }
        }
    }
}

// ------------------------------ K5: zero out --------------------------------
__global__ void zero_kernel(float4* __restrict__ out) {
    const size_t total  = (size_t)EDGES * NNODES / 4;
    const size_t stride = (size_t)gridDim.x * blockDim.x;
    for (size_t i = (size_t)blockIdx.x * blockDim.x + threadIdx.x; i < total; i += stride)
        out[i] = make_float4(0.f, 0.f, 0.f, 0.f);
}

// ----------------- K6: split-K reduce (fixed order) + fc_b ------------------
__global__ void reduce_kernel(const float* __restrict__ fc_b) {
    const int i = blockIdx.x * 256 + threadIdx.x;
    const float4* p = (const float4*)g_Cpart;
    const size_t stride4 = CPART_STRIDE / 4;
    float4 s = p[i];
    float4 v = p[stride4 + i];
    s.x += v.x; s.y += v.y; s.z += v.z; s.w += v.w;
    const int n0 = (i * 4) % DIM;
    float4 bb = *(const float4*)(fc_b + n0);
    s.x += bb.x; s.y += bb.y; s.z += bb.z; s.w += bb.w;
    ((float4*)g_Y)[i] = s;
}

// --------------------------- K7: BN2 stats ----------------------------------
__global__ void bn2_kernel(const float* __restrict__ g2v, const float* __restrict__ be2v) {
    const int b   = blockIdx.x / DIM;
    const int n   = blockIdx.x - b * DIM;
    const int tid = threadIdx.x;

    __shared__ float ssum[256];
    __shared__ float ssq[256];

    float s = 0.f, q = 0.f;
    const float* base = g_Y + (size_t)(b * EDGES) * DIM + n;
#pragma unroll
    for (int u = 0; u < 8; u++) {
        float v = base[(size_t)(tid + u * 256) * DIM];
        s += v; q += v * v;
    }
    ssum[tid] = s; ssq[tid] = q;
    __syncthreads();
    for (int off = 128; off > 0; off >>= 1) {
        if (tid < off) { ssum[tid] += ssum[tid+off]; ssq[tid] += ssq[tid+off]; }
        __syncthreads();
    }
    if (tid == 0) {
        const float inv = 1.0f / (float)EDGES;
        float mu  = ssum[0] * inv;
        float var = ssq[0] * inv - mu * mu;
        float sc  = g2v[n] * rsqrtf(var + 1e-5f);
        g_bn2s[b * DIM + n] = sc;
        g_bn2h[b * DIM + n] = be2v[n] - mu * sc;
    }
}

// ----------------- K8: BN2+ReLU, cosine, scatter to output ------------------
__global__ void final_kernel(const int* __restrict__ o, float* __restrict__ out) {
    const int e    = blockIdx.x * 8 + (threadIdx.x >> 5);
    const int lane = threadIdx.x & 31;

    float dot[3] = {0.f,0.f,0.f}, nx[3] = {0.f,0.f,0.f}, nre = 0.f;
    for (int f = lane; f < DIM; f += 32) {
        float re = bn_relu(g_Y[(size_t)(3 * EDGES + e) * DIM + f],
                           g_bn2s[3 * DIM + f], g_bn2h[3 * DIM + f]);
        nre += re * re;
#pragma unroll
        for (int b = 0; b < 3; b++) {
            float xb = bn_relu(g_Y[(size_t)(b * EDGES + e) * DIM + f],
                               g_bn2s[b * DIM + f], g_bn2h[b * DIM + f]);
            dot[b] += xb * re;
            nx[b]  += xb * xb;
        }
    }
#pragma unroll
    for (int off = 16; off > 0; off >>= 1) {
        nre += __shfl_xor_sync(0xffffffffu, nre, off);
#pragma unroll
        for (int b = 0; b < 3; b++) {
            dot[b] += __shfl_xor_sync(0xffffffffu, dot[b], off);
            nx[b]  += __shfl_xor_sync(0xffffffffu, nx[b], off);
        }
    }
    if (lane == 0) {
        float nr = sqrtf(nre);
        float c = 0.f;
#pragma unroll
        for (int b = 0; b < 3; b++)
            c += dot[b] / fmaxf(sqrtf(nx[b]) * nr, 1e-8f);
        out[(size_t)e * NNODES + o[e]] = c;
    }
}

// ---------------------------------------------------------------------------
extern "C" void kernel_launch(void* const* d_in, const int* in_sizes, int n_in,
                              void* d_out, int out_size) {
    const float* pre_emb  = (const float*)d_in[0];
    const float* r_emb    = (const float*)d_in[1];
    const float* W2       = (const float*)d_in[2];
    const float* b2       = (const float*)d_in[3];
    const float* W3       = (const float*)d_in[4];
    const float* b3       = (const float*)d_in[5];
    const float* W4       = (const float*)d_in[6];
    const float* b4       = (const float*)d_in[7];
    const float* fc_w     = (const float*)d_in[8];
    const float* fc_b     = (const float*)d_in[9];
    const float* g1       = (const float*)d_in[10];
    const float* be1      = (const float*)d_in[11];
    const float* g2       = (const float*)d_in[12];
    const float* be2      = (const float*)d_in[13];
    const int*   src_ids  = (const int*)d_in[14];
    const int*   edge_type= (const int*)d_in[15];
    const int*   p1       = (const int*)d_in[16];
    const int*   p2       = (const int*)d_in[17];
    const int*   p3       = (const int*)d_in[18];
    const int*   o        = (const int*)d_in[19];
    float* out = (float*)d_out;

    cudaFuncSetAttribute(gemm_mma_kernel,
                         cudaFuncAttributeMaxDynamicSharedMemorySize, SMTOT);

    conv_kernel<<<dim3(EDGES, NBLK), 256>>>(pre_emb, r_emb, W2, b2, W3, b3, W4, b4,
                                            src_ids, edge_type, p1, p2, p3);
    statsr_kernel<<<NBLK * CH, 256>>>(g1, be1);
    splitAB_kernel<<<A_GROUPS + B_GROUPS, 256>>>(fc_w);
    gemm_mma_kernel<<<dim3(MROWS / 128, GSPLIT), 256, SMTOT>>>();
    zero_kernel<<<4096, 256>>>((float4*)out);
    reduce_kernel<<<(MROWS * DIM / 4) / 256, 256>>>(fc_b);
    bn2_kernel<<<NBLK * DIM, 256>>>(g2, be2);
    final_kernel<<<EDGES / 8, 256>>>(o, out);
}